// round 10
// baseline (speedup 1.0000x reference)
#include <cuda_runtime.h>
#include <cuda_bf16.h>
#include <cstdint>

#define NTOK   2744
#define NPAD   2816           // 22 * 128
#define KSTACK 384
#define BATCH  4
#define CMID   256
#define CIN    1024
#define COUT   1024
#define NHEADS 4
#define DHEAD  64
#define WDIM   14
#define LOG2E  1.44269504f

// ---------------- scratch (static device memory; no allocations) ----------------
__device__ float g_y1 [BATCH*CMID*NTOK];
__device__ float g_qkv[BATCH*3*CMID*NTOK];                 // [b][768][NTOK] (q|k|v)
__device__ float g_rel[NHEADS*DHEAD*NTOK];
__device__ float g_ao [BATCH*CMID*NTOK];
__device__ float g_y3 [BATCH*COUT*NTOK];
__device__ float g_mean[1024];
__device__ float g_istd[1024];
__device__ __nv_bfloat16 g_xa[(size_t)BATCH*NHEADS*NPAD*KSTACK];   // [z][n][384]
__device__ __nv_bfloat16 g_yb[(size_t)BATCH*NHEADS*NPAD*KSTACK];   // [z][m][384]
__device__ __nv_bfloat16 g_vhi[(size_t)BATCH*NHEADS*NPAD*DHEAD];
__device__ __nv_bfloat16 g_vlo[(size_t)BATCH*NHEADS*NPAD*DHEAD];
// bf16-split GEMM operands
__device__ __nv_bfloat16 g_w1st  [(size_t)CMID*3*CIN];
__device__ __nv_bfloat16 g_wqkvst[(size_t)3*CMID*3*CMID];
__device__ __nv_bfloat16 g_w3st  [(size_t)COUT*3*CMID];
__device__ __nv_bfloat16 g_xst   [(size_t)BATCH*NPAD*3*CIN];
__device__ __nv_bfloat16 g_y1st  [(size_t)BATCH*NPAD*3*CMID];
__device__ __nv_bfloat16 g_aost  [(size_t)BATCH*NPAD*3*CMID];

__device__ __forceinline__ uint32_t smem_u32(const void* p) {
    uint32_t a;
    asm("{ .reg .u64 t; cvta.to.shared.u64 t, %1; cvt.u32.u64 %0, t; }" : "=r"(a) : "l"(p));
    return a;
}
__device__ __forceinline__ uint32_t pack_bf2(float x, float y) {
    __nv_bfloat162 t = __floats2bfloat162_rn(x, y);
    return *(uint32_t*)&t;
}

// ---------------- rel position tensor ----------------
__global__ void build_rel_kernel(const float* __restrict__ rh,
                                 const float* __restrict__ rw,
                                 const float* __restrict__ rd) {
    int idx = blockIdx.x * 256 + threadIdx.x;
    int n  = idx % NTOK;
    int hd = idx / NTOK;
    int w  = n / (WDIM*WDIM);
    int hh = (n / WDIM) % WDIM;
    int dd = n % WDIM;
    g_rel[idx] = rh[(hd*WDIM + hh)*WDIM + dd]
               + rw[(hd*WDIM + w )*WDIM + dd]
               + rd[(hd*WDIM + w )*WDIM + hh];
}

// ---------------- weight split: W[M][K] -> Wst[M][3K] = [hi|lo|hi] ----------------
__global__ void wsplit(const float* __restrict__ W, __nv_bfloat16* __restrict__ Wst,
                       int total, int K) {
    int idx = blockIdx.x * 256 + threadIdx.x;
    if (idx >= total) return;
    int m = idx / K, k = idx - m*K;
    float v = W[idx];
    __nv_bfloat16 hi = __float2bfloat16(v);
    __nv_bfloat16 lo = __float2bfloat16(v - __bfloat162float(hi));
    size_t base = (size_t)m * 3 * K;
    Wst[base + k]       = hi;
    Wst[base + K + k]   = lo;
    Wst[base + 2*K + k] = hi;
}

// ---------------- activation split+transpose (+optional BN-ReLU) ----------------
__global__ void xsplit(const float* __restrict__ X, __nv_bfloat16* __restrict__ Xst,
                       int C, long strideX, long strideXst,
                       const float* __restrict__ mean, const float* __restrict__ istd,
                       const float* __restrict__ gam, const float* __restrict__ bet) {
    __shared__ float t[32][33];
    const int n0 = blockIdx.x * 32, c0 = blockIdx.y * 32, z = blockIdx.z;
    const int tx = threadIdx.x, ty = threadIdx.y;   // 32 x 8
    #pragma unroll
    for (int r = 0; r < 4; r++) {
        int c = c0 + ty + r*8;
        int n = n0 + tx;
        float v = 0.f;
        if (n < NTOK) {
            v = X[z*strideX + (size_t)c*NTOK + n];
            if (mean) v = fmaxf((v - mean[c]) * istd[c] * gam[c] + bet[c], 0.f);
        }
        t[ty + r*8][tx] = v;
    }
    __syncthreads();
    #pragma unroll
    for (int r = 0; r < 4; r++) {
        int n = n0 + ty + r*8;
        int c = c0 + tx;
        float v = t[tx][ty + r*8];
        __nv_bfloat16 hi = __float2bfloat16(v);
        __nv_bfloat16 lo = __float2bfloat16(v - __bfloat162float(hi));
        size_t base = z*strideXst + (size_t)n * (3*C);
        Xst[base + c]       = hi;
        Xst[base + C + c]   = hi;
        Xst[base + 2*C + c] = lo;
    }
}

// ---------------- generic HMMA GEMM (convs/qkv) ----------------
__global__ __launch_bounds__(256) void gemm_hmma(
    const __nv_bfloat16* __restrict__ A, const __nv_bfloat16* __restrict__ B,
    float* __restrict__ C, int Ks, long strideB, long strideC,
    const float* __restrict__ bias0, const float* __restrict__ bias1,
    const float* __restrict__ bias2)
{
    __shared__ __nv_bfloat16 As[2][128*24];
    __shared__ __nv_bfloat16 Bs[2][128*24];
    const int tid = threadIdx.x;
    const int warp = tid >> 5, lane = tid & 31;
    const int wm = warp >> 2, wn = warp & 3;
    const int z = blockIdx.z;
    const int bm = blockIdx.y * 128, n0 = blockIdx.x * 128;

    const __nv_bfloat16* gA = A + (size_t)(bm + (tid >> 1))*Ks;
    const __nv_bfloat16* gB = B + z*strideB + (size_t)(n0 + (tid >> 1))*Ks;
    const int lrow  = tid >> 1;
    const int lhalf = (tid & 1) * 8;

    const uint32_t sa_base = smem_u32(As);
    const uint32_t sb_base = smem_u32(Bs);
    const int arow = lane & 15, asel = lane >> 4;
    const int brow = lane & 7,  bsel = (lane >> 3) & 1;

    float acc[4][4][4] = {};
    const int steps = Ks >> 4;

    uint4 pa = *(const uint4*)(gA + lhalf);
    uint4 pb = *(const uint4*)(gB + lhalf);

    #pragma unroll 1
    for (int s = 0; s < steps; s++) {
        const int buf = s & 1;
        *(uint4*)&As[buf][lrow*24 + lhalf] = pa;
        *(uint4*)&Bs[buf][lrow*24 + lhalf] = pb;
        __syncthreads();

        if (s + 1 < steps) {
            const int k0 = (s + 1) * 16;
            pa = *(const uint4*)(gA + k0 + lhalf);
            pb = *(const uint4*)(gB + k0 + lhalf);
        }

        uint32_t afr[4][4];
        #pragma unroll
        for (int i = 0; i < 4; i++) {
            const int row = wm*64 + i*16 + arow;
            const uint32_t addr = sa_base + (uint32_t)(buf*128*24 + row*24 + asel*8) * 2;
            asm volatile("ldmatrix.sync.aligned.m8n8.x4.shared.b16 {%0,%1,%2,%3}, [%4];"
                : "=r"(afr[i][0]), "=r"(afr[i][1]), "=r"(afr[i][2]), "=r"(afr[i][3]) : "r"(addr));
        }
        uint32_t bfr[4][2];
        #pragma unroll
        for (int j = 0; j < 4; j++) {
            const int row = wn*32 + j*8 + brow;
            const uint32_t addr = sb_base + (uint32_t)(buf*128*24 + row*24 + bsel*8) * 2;
            asm volatile("ldmatrix.sync.aligned.m8n8.x2.shared.b16 {%0,%1}, [%2];"
                : "=r"(bfr[j][0]), "=r"(bfr[j][1]) : "r"(addr));
        }
        #pragma unroll
        for (int i = 0; i < 4; i++)
            #pragma unroll
            for (int j = 0; j < 4; j++)
                asm volatile(
                    "mma.sync.aligned.m16n8k16.row.col.f32.bf16.bf16.f32 "
                    "{%0,%1,%2,%3}, {%4,%5,%6,%7}, {%8,%9}, {%0,%1,%2,%3};"
                    : "+f"(acc[i][j][0]), "+f"(acc[i][j][1]), "+f"(acc[i][j][2]), "+f"(acc[i][j][3])
                    : "r"(afr[i][0]), "r"(afr[i][1]), "r"(afr[i][2]), "r"(afr[i][3]),
                      "r"(bfr[j][0]), "r"(bfr[j][1]));
    }

    float* Cz = C + z*strideC;
    const int gr = lane >> 2, gc = (lane & 3) * 2;
    #pragma unroll
    for (int i = 0; i < 4; i++) {
        const int r0 = bm + wm*64 + i*16 + gr;
        const int r1 = r0 + 8;
        float bi0 = 0.f, bi1 = 0.f;
        if (bias0) {
            const float* bp0 = (r0 < 256) ? bias0 : (r0 < 512) ? bias1 : bias2;
            const float* bp1 = (r1 < 256) ? bias0 : (r1 < 512) ? bias1 : bias2;
            bi0 = bp0[r0 & 255];
            bi1 = bp1[r1 & 255];
        }
        #pragma unroll
        for (int j = 0; j < 4; j++) {
            const int col = n0 + wn*32 + j*8 + gc;
            if (col < NTOK) {
                *(float2*)&Cz[(size_t)r0*NTOK + col] = make_float2(acc[i][j][0] + bi0, acc[i][j][1] + bi0);
                *(float2*)&Cz[(size_t)r1*NTOK + col] = make_float2(acc[i][j][2] + bi1, acc[i][j][3] + bi1);
            }
        }
    }
}

// ---------------- build bf16-split stacked operands xa=[Ahi|Alo|Ahi], yb=[Bhi|Bhi|Blo] ----------------
__global__ void build_xy() {
    __shared__ float ta[32][33], tb[32][33];
    const int n0 = blockIdx.x * 32, c0 = blockIdx.y * 32, z = blockIdx.z;
    const int b = z >> 2, h = z & 3;
    const int tx = threadIdx.x, ty = threadIdx.y;    // 32 x 8
    #pragma unroll
    for (int r = 0; r < 4; r++) {
        int col = c0 + ty + r*8;
        int n = n0 + tx;
        float va = 0.f, vb = 0.f;
        if (n < NTOK) {
            if (col < 64) {
                va = g_qkv[((size_t)b*768 + h*64 + col)*NTOK + n];
                vb = g_qkv[((size_t)b*768 + 256 + h*64 + col)*NTOK + n];
            } else {
                va = g_rel[(size_t)(h*64 + col - 64)*NTOK + n];
                vb = g_qkv[((size_t)b*768 + h*64 + col - 64)*NTOK + n];
            }
        }
        ta[ty + r*8][tx] = va;
        tb[ty + r*8][tx] = vb;
    }
    __syncthreads();
    #pragma unroll
    for (int r = 0; r < 4; r++) {
        int n = n0 + ty + r*8;
        size_t base = ((size_t)z*NPAD + n)*KSTACK;
        int col = c0 + tx;
        float va = ta[tx][ty + r*8];
        float vb = tb[tx][ty + r*8];
        __nv_bfloat16 ha = __float2bfloat16(va);
        __nv_bfloat16 la = __float2bfloat16(va - __bfloat162float(ha));
        __nv_bfloat16 hb = __float2bfloat16(vb);
        __nv_bfloat16 lb = __float2bfloat16(vb - __bfloat162float(hb));
        g_xa[base + col]       = ha;
        g_xa[base + 128 + col] = la;
        g_xa[base + 256 + col] = ha;
        g_yb[base + col]       = hb;
        g_yb[base + 128 + col] = hb;
        g_yb[base + 256 + col] = lb;
    }
}

// ---------------- V split ----------------
__global__ void vsplit() {
    __shared__ float t[32][33];
    const int m0 = blockIdx.x * 32, c0 = blockIdx.y * 32, z = blockIdx.z;
    const int b = z >> 2, h = z & 3;
    const int tx = threadIdx.x, ty = threadIdx.y;   // 32 x 8
    #pragma unroll
    for (int r = 0; r < 4; r++) {
        int c = c0 + ty + r*8;
        int m = m0 + tx;
        t[ty + r*8][tx] = (m < NTOK) ? g_qkv[((size_t)b*768 + 512 + h*64 + c)*NTOK + m] : 0.f;
    }
    __syncthreads();
    #pragma unroll
    for (int r = 0; r < 4; r++) {
        int m = m0 + ty + r*8;
        float v = t[tx][ty + r*8];
        __nv_bfloat16 hi = __float2bfloat16(v);
        __nv_bfloat16 lo = __float2bfloat16(v - __bfloat162float(hi));
        size_t idx = ((size_t)z*NPAD + m)*DHEAD + c0 + tx;
        g_vhi[idx] = hi;
        g_vlo[idx] = lo;
    }
}

// ---------------- fused flash attention (HMMA): S + online softmax + PV, no S materialization ----------------
// grid (22 n-tiles, 16 z), 256 thr = 8 warps, each warp owns 16 rows.
// dyn smem: A persistent [128][392], B double [2][128*24], Vhi/Vlo [128*72].
#define APITCH 392
__global__ __launch_bounds__(256) void flash_mma() {
    extern __shared__ __nv_bfloat16 sm[];
    __nv_bfloat16* Asm = sm;              // 128*392 = 50176
    __nv_bfloat16* Bsm = sm + 50176;      // 2*128*24 = 6144
    __nv_bfloat16* Vhs = sm + 56320;      // 128*72 = 9216
    __nv_bfloat16* Vls = sm + 65536;      // 128*72

    const int tid = threadIdx.x;
    const int warp = tid >> 5, lane = tid & 31;
    const int z = blockIdx.y, b = z >> 2, h = z & 3;
    const int n0 = blockIdx.x * 128;
    const int wrow = warp * 16;

    const __nv_bfloat16* xa  = g_xa  + ((size_t)z*NPAD + n0)*KSTACK;
    const __nv_bfloat16* yb  = g_yb  + (size_t)z*NPAD*KSTACK;
    const __nv_bfloat16* vhi = g_vhi + (size_t)z*NPAD*DHEAD;
    const __nv_bfloat16* vlo = g_vlo + (size_t)z*NPAD*DHEAD;

    // ---- load persistent A (n-rows x 384) ----
    #pragma unroll
    for (int i = 0; i < 24; i++) {
        int id = tid + 256*i;
        int row = id / 48, seg = id % 48;
        *(uint4*)(Asm + row*APITCH + seg*8) = *(const uint4*)(xa + (size_t)row*KSTACK + seg*8);
    }

    const uint32_t sa  = smem_u32(Asm);
    const uint32_t sb  = smem_u32(Bsm);
    const uint32_t svh = smem_u32(Vhs);
    const uint32_t svl = smem_u32(Vls);

    const int brow_ld = tid >> 1;
    const int bhalf   = (tid & 1) * 8;

    float O[8][4] = {};
    float Mr0 = -1e30f, Mr1 = -1e30f, Lr0 = 0.f, Lr1 = 0.f;

    const uint32_t a_addr0 = sa + (uint32_t)((wrow + (lane & 15))*APITCH + ((lane >> 4) << 3)) * 2;

    #pragma unroll 1
    for (int mt = 0; mt < 22; mt++) {
        const int m0 = mt * 128;
        float Sa[16][4];
        #pragma unroll
        for (int j = 0; j < 16; j++) { Sa[j][0]=0.f; Sa[j][1]=0.f; Sa[j][2]=0.f; Sa[j][3]=0.f; }

        const __nv_bfloat16* ybm = yb + (size_t)(m0 + brow_ld)*KSTACK;
        uint4 pb = *(const uint4*)(ybm + bhalf);

        // ---- S = A . B^T over K=384 ----
        #pragma unroll 1
        for (int s = 0; s < 24; s++) {
            const int buf = s & 1;
            *(uint4*)(Bsm + buf*3072 + brow_ld*24 + bhalf) = pb;
            __syncthreads();
            if (s + 1 < 24) pb = *(const uint4*)(ybm + (s+1)*16 + bhalf);

            uint32_t af[4];
            const uint32_t aaddr = a_addr0 + (uint32_t)(s*16)*2;
            asm volatile("ldmatrix.sync.aligned.m8n8.x4.shared.b16 {%0,%1,%2,%3}, [%4];"
                : "=r"(af[0]), "=r"(af[1]), "=r"(af[2]), "=r"(af[3]) : "r"(aaddr));

            #pragma unroll
            for (int jp = 0; jp < 8; jp++) {
                uint32_t bf[4];
                const uint32_t baddr = sb + (uint32_t)(buf*3072 +
                    ((jp*2 + (lane>>4))*8 + (lane&7))*24 + ((lane>>3)&1)*8) * 2;
                asm volatile("ldmatrix.sync.aligned.m8n8.x4.shared.b16 {%0,%1,%2,%3}, [%4];"
                    : "=r"(bf[0]), "=r"(bf[1]), "=r"(bf[2]), "=r"(bf[3]) : "r"(baddr));
                asm volatile("mma.sync.aligned.m16n8k16.row.col.f32.bf16.bf16.f32 "
                    "{%0,%1,%2,%3}, {%4,%5,%6,%7}, {%8,%9}, {%0,%1,%2,%3};"
                    : "+f"(Sa[2*jp][0]), "+f"(Sa[2*jp][1]), "+f"(Sa[2*jp][2]), "+f"(Sa[2*jp][3])
                    : "r"(af[0]), "r"(af[1]), "r"(af[2]), "r"(af[3]), "r"(bf[0]), "r"(bf[1]));
                asm volatile("mma.sync.aligned.m16n8k16.row.col.f32.bf16.bf16.f32 "
                    "{%0,%1,%2,%3}, {%4,%5,%6,%7}, {%8,%9}, {%0,%1,%2,%3};"
                    : "+f"(Sa[2*jp+1][0]), "+f"(Sa[2*jp+1][1]), "+f"(Sa[2*jp+1][2]), "+f"(Sa[2*jp+1][3])
                    : "r"(af[0]), "r"(af[1]), "r"(af[2]), "r"(af[3]), "r"(bf[2]), "r"(bf[3]));
            }
        }

        // ---- mask invalid m columns (last tile only) ----
        if (mt == 21) {
            #pragma unroll
            for (int j = 0; j < 16; j++) {
                const int col = m0 + j*8 + 2*(lane & 3);
                if (col >= NTOK)     { Sa[j][0] = -1e30f; Sa[j][2] = -1e30f; }
                if (col + 1 >= NTOK) { Sa[j][1] = -1e30f; Sa[j][3] = -1e30f; }
            }
        }

        // ---- online softmax (intra-warp: shfl over 4-lane row groups) ----
        float mx0 = -1e30f, mx1 = -1e30f;
        #pragma unroll
        for (int j = 0; j < 16; j++) {
            mx0 = fmaxf(mx0, fmaxf(Sa[j][0], Sa[j][1]));
            mx1 = fmaxf(mx1, fmaxf(Sa[j][2], Sa[j][3]));
        }
        mx0 = fmaxf(mx0, __shfl_xor_sync(0xffffffffu, mx0, 1));
        mx0 = fmaxf(mx0, __shfl_xor_sync(0xffffffffu, mx0, 2));
        mx1 = fmaxf(mx1, __shfl_xor_sync(0xffffffffu, mx1, 1));
        mx1 = fmaxf(mx1, __shfl_xor_sync(0xffffffffu, mx1, 2));
        const float mn0 = fmaxf(Mr0, mx0), mn1 = fmaxf(Mr1, mx1);
        const float al0 = exp2f((Mr0 - mn0) * LOG2E);
        const float al1 = exp2f((Mr1 - mn1) * LOG2E);
        float s0 = 0.f, s1 = 0.f;
        #pragma unroll
        for (int j = 0; j < 16; j++) {
            Sa[j][0] = exp2f((Sa[j][0] - mn0) * LOG2E); s0 += Sa[j][0];
            Sa[j][1] = exp2f((Sa[j][1] - mn0) * LOG2E); s0 += Sa[j][1];
            Sa[j][2] = exp2f((Sa[j][2] - mn1) * LOG2E); s1 += Sa[j][2];
            Sa[j][3] = exp2f((Sa[j][3] - mn1) * LOG2E); s1 += Sa[j][3];
        }
        s0 += __shfl_xor_sync(0xffffffffu, s0, 1);
        s0 += __shfl_xor_sync(0xffffffffu, s0, 2);
        s1 += __shfl_xor_sync(0xffffffffu, s1, 1);
        s1 += __shfl_xor_sync(0xffffffffu, s1, 2);
        Lr0 = Lr0 * al0 + s0;
        Lr1 = Lr1 * al1 + s1;
        Mr0 = mn0; Mr1 = mn1;
        #pragma unroll
        for (int dj = 0; dj < 8; dj++) {
            O[dj][0] *= al0; O[dj][1] *= al0;
            O[dj][2] *= al1; O[dj][3] *= al1;
        }

        // ---- load V tile (hi/lo): 128 m-rows x 64 d ----
        __syncthreads();   // prior PV reads of V smem done
        #pragma unroll
        for (int i = 0; i < 4; i++) {
            const int idx = tid + 256*i;          // 0..1023
            const int row = idx >> 3, seg = (idx & 7) * 8;
            const size_t gsrc = (size_t)(m0 + row)*DHEAD + seg;
            *(uint4*)(Vhs + row*72 + seg) = *(const uint4*)(vhi + gsrc);
            *(uint4*)(Vls + row*72 + seg) = *(const uint4*)(vlo + gsrc);
        }
        __syncthreads();

        // ---- O += P . V  (k = m dimension, 8 k16 steps; 3-term split) ----
        #pragma unroll
        for (int ks = 0; ks < 8; ks++) {
            uint32_t phi[4], plo[4];
            {
                const float x0 = Sa[2*ks][0],   x1 = Sa[2*ks][1];
                const float x2 = Sa[2*ks][2],   x3 = Sa[2*ks][3];
                const float y0 = Sa[2*ks+1][0], y1 = Sa[2*ks+1][1];
                const float y2 = Sa[2*ks+1][2], y3 = Sa[2*ks+1][3];
                phi[0] = pack_bf2(x0, x1); phi[1] = pack_bf2(x2, x3);
                phi[2] = pack_bf2(y0, y1); phi[3] = pack_bf2(y2, y3);
                plo[0] = pack_bf2(x0 - __bfloat162float(__float2bfloat16(x0)),
                                  x1 - __bfloat162float(__float2bfloat16(x1)));
                plo[1] = pack_bf2(x2 - __bfloat162float(__float2bfloat16(x2)),
                                  x3 - __bfloat162float(__float2bfloat16(x3)));
                plo[2] = pack_bf2(y0 - __bfloat162float(__float2bfloat16(y0)),
                                  y1 - __bfloat162float(__float2bfloat16(y1)));
                plo[3] = pack_bf2(y2 - __bfloat162float(__float2bfloat16(y2)),
                                  y3 - __bfloat162float(__float2bfloat16(y3)));
            }
            #pragma unroll
            for (int jj = 0; jj < 4; jj++) {   // d halves of 16
                const uint32_t voff = (uint32_t)((ks*16 + (lane & 7) + ((lane >> 3) & 1)*8)*72
                                                 + jj*16 + ((lane >> 4) << 3)) * 2;
                uint32_t bh[4], bl[4];
                asm volatile("ldmatrix.sync.aligned.m8n8.x4.trans.shared.b16 {%0,%1,%2,%3}, [%4];"
                    : "=r"(bh[0]), "=r"(bh[1]), "=r"(bh[2]), "=r"(bh[3]) : "r"(svh + voff));
                asm volatile("ldmatrix.sync.aligned.m8n8.x4.trans.shared.b16 {%0,%1,%2,%3}, [%4];"
                    : "=r"(bl[0]), "=r"(bl[1]), "=r"(bl[2]), "=r"(bl[3]) : "r"(svl + voff));
                #define PV_MMA(ac, af, b0, b1) \
                    asm volatile("mma.sync.aligned.m16n8k16.row.col.f32.bf16.bf16.f32 " \
                        "{%0,%1,%2,%3}, {%4,%5,%6,%7}, {%8,%9}, {%0,%1,%2,%3};" \
                        : "+f"((ac)[0]), "+f"((ac)[1]), "+f"((ac)[2]), "+f"((ac)[3]) \
                        : "r"((af)[0]), "r"((af)[1]), "r"((af)[2]), "r"((af)[3]), "r"(b0), "r"(b1))
                PV_MMA(O[2*jj],   phi, bh[0], bh[1]);
                PV_MMA(O[2*jj+1], phi, bh[2], bh[3]);
                PV_MMA(O[2*jj],   plo, bh[0], bh[1]);
                PV_MMA(O[2*jj+1], plo, bh[2], bh[3]);
                PV_MMA(O[2*jj],   phi, bl[0], bl[1]);
                PV_MMA(O[2*jj+1], phi, bl[2], bl[3]);
                #undef PV_MMA
            }
        }
        __syncthreads();   // PV reads done before next m-tile's B/V writes
    }

    // ---- epilogue: O / L -> g_ao[c][n] ----
    const float inv0 = 1.f / Lr0, inv1 = 1.f / Lr1;
    const int baseCh = b*CMID + h*DHEAD;
    const int r0 = n0 + wrow + (lane >> 2);
    const int r1 = r0 + 8;
    #pragma unroll
    for (int dj = 0; dj < 8; dj++) {
        const int d = dj*8 + 2*(lane & 3);
        float* c0p = g_ao + (size_t)(baseCh + d)*NTOK;
        float* c1p = g_ao + (size_t)(baseCh + d + 1)*NTOK;
        if (r0 < NTOK) { c0p[r0] = O[dj][0]*inv0; c1p[r0] = O[dj][1]*inv0; }
        if (r1 < NTOK) { c0p[r1] = O[dj][2]*inv1; c1p[r1] = O[dj][3]*inv1; }
    }
}

// ---------------- BatchNorm ----------------
__global__ __launch_bounds__(256) void bn_stats(const float* __restrict__ x, int C,
                                                float* __restrict__ mean, float* __restrict__ istd) {
    const int c = blockIdx.x;
    const int tid = threadIdx.x;
    const int lane = tid & 31, wid = tid >> 5;
    float s = 0.f, sq = 0.f;
    for (int i = tid; i < BATCH*NTOK; i += 256) {
        int b = i / NTOK, n = i - b*NTOK;
        float v = x[((long)b*C + c)*NTOK + n];
        s += v; sq += v*v;
    }
    #pragma unroll
    for (int d = 16; d > 0; d >>= 1) {
        s  += __shfl_xor_sync(0xffffffffu, s, d);
        sq += __shfl_xor_sync(0xffffffffu, sq, d);
    }
    __shared__ float r1[8], r2[8];
    if (lane == 0) { r1[wid] = s; r2[wid] = sq; }
    __syncthreads();
    if (tid == 0) {
        float S1 = 0.f, S2 = 0.f;
        #pragma unroll
        for (int w = 0; w < 8; w++) { S1 += r1[w]; S2 += r2[w]; }
        const float inv_cnt = 1.f / (BATCH*NTOK);
        float m = S1 * inv_cnt;
        float var = S2 * inv_cnt - m*m;
        mean[c] = m;
        istd[c] = rsqrtf(var + 1e-5f);
    }
}

__global__ void bn_res_relu(const float* __restrict__ y, const float* __restrict__ xres,
                            float* __restrict__ out,
                            const float* __restrict__ mean, const float* __restrict__ istd,
                            const float* __restrict__ g, const float* __restrict__ bp) {
    long idx = (long)blockIdx.x * 256 + threadIdx.x;
    if (idx >= (long)BATCH*COUT*NTOK) return;
    int c = (int)((idx / NTOK) % COUT);
    float v = (y[idx] - mean[c]) * istd[c] * g[c] + bp[c] + xres[idx];
    out[idx] = fmaxf(v, 0.f);
}

// ---------------- launch ----------------
extern "C" void kernel_launch(void* const* d_in, const int* in_sizes, int n_in,
                              void* d_out, int out_size) {
    const float* x    = (const float*)d_in[0];
    const float* W1   = (const float*)d_in[1];
    const float* g1   = (const float*)d_in[2];
    const float* b1   = (const float*)d_in[3];
    const float* Wq   = (const float*)d_in[4];
    const float* bq   = (const float*)d_in[5];
    const float* Wk   = (const float*)d_in[6];
    const float* bk   = (const float*)d_in[7];
    const float* Wv   = (const float*)d_in[8];
    const float* bv   = (const float*)d_in[9];
    const float* relh = (const float*)d_in[10];
    const float* relw = (const float*)d_in[11];
    const float* reld = (const float*)d_in[12];
    const float* g2   = (const float*)d_in[13];
    const float* b2   = (const float*)d_in[14];
    const float* W3   = (const float*)d_in[15];
    const float* g3   = (const float*)d_in[16];
    const float* b3   = (const float*)d_in[17];
    float* out = (float*)d_out;

    float *y1, *ao, *y3, *mean, *istd, *qkv;
    __nv_bfloat16 *w1st, *wqkvst, *w3st, *xst, *y1st, *aost;
    cudaGetSymbolAddress((void**)&y1,  g_y1);
    cudaGetSymbolAddress((void**)&ao,  g_ao);
    cudaGetSymbolAddress((void**)&y3,  g_y3);
    cudaGetSymbolAddress((void**)&mean,g_mean);
    cudaGetSymbolAddress((void**)&istd,g_istd);
    cudaGetSymbolAddress((void**)&qkv, g_qkv);
    cudaGetSymbolAddress((void**)&w1st,  g_w1st);
    cudaGetSymbolAddress((void**)&wqkvst,g_wqkvst);
    cudaGetSymbolAddress((void**)&w3st,  g_w3st);
    cudaGetSymbolAddress((void**)&xst,   g_xst);
    cudaGetSymbolAddress((void**)&y1st,  g_y1st);
    cudaGetSymbolAddress((void**)&aost,  g_aost);

    const dim3 blk(256);
    const int NT = (NTOK + 127) / 128;        // 22
    const int NT32 = NPAD / 32;               // 88
    const int FL_SMEM = (50176 + 6144 + 2*9216) * 2;   // 149504 B
    cudaFuncSetAttribute(flash_mma, cudaFuncAttributeMaxDynamicSharedMemorySize, FL_SMEM);

    // weight splits
    wsplit<<<(CMID*CIN + 255)/256, blk>>>(W1, w1st, CMID*CIN, CIN);
    wsplit<<<(CMID*CMID + 255)/256, blk>>>(Wq, wqkvst,                    CMID*CMID, CMID);
    wsplit<<<(CMID*CMID + 255)/256, blk>>>(Wk, wqkvst + (size_t)256*768,  CMID*CMID, CMID);
    wsplit<<<(CMID*CMID + 255)/256, blk>>>(Wv, wqkvst + (size_t)512*768,  CMID*CMID, CMID);
    wsplit<<<(COUT*CMID + 255)/256, blk>>>(W3, w3st, COUT*CMID, CMID);

    // x split -> conv1 (HMMA)
    xsplit<<<dim3(NT32, CIN/32, BATCH), dim3(32,8)>>>(x, xst, CIN,
        (long)CIN*NTOK, (long)NPAD*3*CIN, nullptr, nullptr, nullptr, nullptr);
    gemm_hmma<<<dim3(NT, 2, BATCH), blk>>>(w1st, xst, y1, 3*CIN,
        (long)NPAD*3*CIN, (long)CMID*NTOK, nullptr, nullptr, nullptr);
    bn_stats<<<CMID, 256>>>(y1, CMID, mean, istd);

    // BN1+ReLU fused into split -> qkv (HMMA, stacked M=768)
    xsplit<<<dim3(NT32, CMID/32, BATCH), dim3(32,8)>>>(y1, y1st, CMID,
        (long)CMID*NTOK, (long)NPAD*3*CMID, mean, istd, g1, b1);
    gemm_hmma<<<dim3(NT, 6, BATCH), blk>>>(wqkvst, y1st, qkv, 3*CMID,
        (long)NPAD*3*CMID, (long)768*NTOK, bq, bk, bv);

    // rel tensor + attention operand prep
    build_rel_kernel<<<(NHEADS*DHEAD*NTOK)/256, 256>>>(relh, relw, reld);
    build_xy<<<dim3(NT32, 4, BATCH*NHEADS), dim3(32,8)>>>();
    vsplit<<<dim3(NT32, 2, BATCH*NHEADS), dim3(32,8)>>>();

    // fused flash attention (no S materialization)
    flash_mma<<<dim3(NT, BATCH*NHEADS), blk, FL_SMEM>>>();

    // BN2+ReLU fused into split -> conv3 (HMMA)
    bn_stats<<<CMID, 256>>>(ao, CMID, mean, istd);
    xsplit<<<dim3(NT32, CMID/32, BATCH), dim3(32,8)>>>(ao, aost, CMID,
        (long)CMID*NTOK, (long)NPAD*3*CMID, mean, istd, g2, b2);
    gemm_hmma<<<dim3(NT, 8, BATCH), blk>>>(w3st, aost, y3, 3*CMID,
        (long)NPAD*3*CMID, (long)COUT*NTOK, nullptr, nullptr, nullptr);

    // BN3 + residual + ReLU
    bn_stats<<<COUT, 256>>>(y3, COUT, mean, istd);
    bn_res_relu<<<(BATCH*COUT*NTOK)/256, 256>>>(y3, x, out, mean, istd, g3, b3);
}

// round 11
// speedup vs baseline: 1.2130x; 1.2130x over previous
#include <cuda_runtime.h>
#include <cuda_bf16.h>
#include <cstdint>

#define NTOK   2744
#define NPAD   2816           // 22 * 128
#define KSTACK 384
#define BATCH  4
#define CMID   256
#define CIN    1024
#define COUT   1024
#define NHEADS 4
#define DHEAD  64
#define WDIM   14
#define LOG2E  1.44269504f

// ---------------- scratch (static device memory; no allocations) ----------------
__device__ float g_y1 [BATCH*CMID*NTOK];
__device__ float g_qkv[BATCH*3*CMID*NTOK];                 // [b][768][NTOK] (q|k|v)
__device__ float g_rel[NHEADS*DHEAD*NTOK];
__device__ float g_S  [(size_t)BATCH*NHEADS*NTOK*NTOK];    // ~482 MB
__device__ float g_ao [BATCH*CMID*NTOK];
__device__ float g_y3 [BATCH*COUT*NTOK];
__device__ float g_mean[1024];
__device__ float g_istd[1024];
__device__ __nv_bfloat16 g_xa[(size_t)BATCH*NHEADS*NPAD*KSTACK];   // [z][n][384]
__device__ __nv_bfloat16 g_yb[(size_t)BATCH*NHEADS*NPAD*KSTACK];   // [z][m][384]
__device__ __nv_bfloat16 g_vhi[(size_t)BATCH*NHEADS*NPAD*DHEAD];
__device__ __nv_bfloat16 g_vlo[(size_t)BATCH*NHEADS*NPAD*DHEAD];
__device__ float g_rmax [BATCH*NHEADS*NPAD];
// bf16-split GEMM operands
__device__ __nv_bfloat16 g_w1st  [(size_t)CMID*3*CIN];
__device__ __nv_bfloat16 g_wqkvst[(size_t)3*CMID*3*CMID];
__device__ __nv_bfloat16 g_w3st  [(size_t)COUT*3*CMID];
__device__ __nv_bfloat16 g_xst   [(size_t)BATCH*NPAD*3*CIN];
__device__ __nv_bfloat16 g_y1st  [(size_t)BATCH*NPAD*3*CMID];
__device__ __nv_bfloat16 g_aost  [(size_t)BATCH*NPAD*3*CMID];

__device__ __forceinline__ uint32_t smem_u32(const void* p) {
    uint32_t a;
    asm("{ .reg .u64 t; cvta.to.shared.u64 t, %1; cvt.u32.u64 %0, t; }" : "=r"(a) : "l"(p));
    return a;
}
__device__ __forceinline__ void atomicMaxF(float* addr, float val) {
    if (val >= 0.f) atomicMax((int*)addr, __float_as_int(val));
    else            atomicMin((unsigned int*)addr, __float_as_uint(val));
}

// ---------------- rel position tensor ----------------
__global__ void build_rel_kernel(const float* __restrict__ rh,
                                 const float* __restrict__ rw,
                                 const float* __restrict__ rd) {
    int idx = blockIdx.x * 256 + threadIdx.x;
    int n  = idx % NTOK;
    int hd = idx / NTOK;
    int w  = n / (WDIM*WDIM);
    int hh = (n / WDIM) % WDIM;
    int dd = n % WDIM;
    g_rel[idx] = rh[(hd*WDIM + hh)*WDIM + dd]
               + rw[(hd*WDIM + w )*WDIM + dd]
               + rd[(hd*WDIM + w )*WDIM + hh];
}

// ---------------- weight split: W[M][K] -> Wst[M][3K] = [hi|lo|hi] ----------------
__global__ void wsplit(const float* __restrict__ W, __nv_bfloat16* __restrict__ Wst,
                       int total, int K) {
    int idx = blockIdx.x * 256 + threadIdx.x;
    if (idx >= total) return;
    int m = idx / K, k = idx - m*K;
    float v = W[idx];
    __nv_bfloat16 hi = __float2bfloat16(v);
    __nv_bfloat16 lo = __float2bfloat16(v - __bfloat162float(hi));
    size_t base = (size_t)m * 3 * K;
    Wst[base + k]       = hi;
    Wst[base + K + k]   = lo;
    Wst[base + 2*K + k] = hi;
}

// ---------------- activation split+transpose (+optional BN-ReLU) ----------------
__global__ void xsplit(const float* __restrict__ X, __nv_bfloat16* __restrict__ Xst,
                       int C, long strideX, long strideXst,
                       const float* __restrict__ mean, const float* __restrict__ istd,
                       const float* __restrict__ gam, const float* __restrict__ bet) {
    __shared__ float t[32][33];
    const int n0 = blockIdx.x * 32, c0 = blockIdx.y * 32, z = blockIdx.z;
    const int tx = threadIdx.x, ty = threadIdx.y;   // 32 x 8
    #pragma unroll
    for (int r = 0; r < 4; r++) {
        int c = c0 + ty + r*8;
        int n = n0 + tx;
        float v = 0.f;
        if (n < NTOK) {
            v = X[z*strideX + (size_t)c*NTOK + n];
            if (mean) v = fmaxf((v - mean[c]) * istd[c] * gam[c] + bet[c], 0.f);
        }
        t[ty + r*8][tx] = v;
    }
    __syncthreads();
    #pragma unroll
    for (int r = 0; r < 4; r++) {
        int n = n0 + ty + r*8;
        int c = c0 + tx;
        float v = t[tx][ty + r*8];
        __nv_bfloat16 hi = __float2bfloat16(v);
        __nv_bfloat16 lo = __float2bfloat16(v - __bfloat162float(hi));
        size_t base = z*strideXst + (size_t)n * (3*C);
        Xst[base + c]       = hi;
        Xst[base + C + c]   = hi;
        Xst[base + 2*C + c] = lo;
    }
}

// ---------------- generic HMMA GEMM (convs/qkv) ----------------
__global__ __launch_bounds__(256) void gemm_hmma(
    const __nv_bfloat16* __restrict__ A, const __nv_bfloat16* __restrict__ B,
    float* __restrict__ C, int Ks, long strideB, long strideC,
    const float* __restrict__ bias0, const float* __restrict__ bias1,
    const float* __restrict__ bias2)
{
    __shared__ __nv_bfloat16 As[2][128*24];
    __shared__ __nv_bfloat16 Bs[2][128*24];
    const int tid = threadIdx.x;
    const int warp = tid >> 5, lane = tid & 31;
    const int wm = warp >> 2, wn = warp & 3;
    const int z = blockIdx.z;
    const int bm = blockIdx.y * 128, n0 = blockIdx.x * 128;

    const __nv_bfloat16* gA = A + (size_t)(bm + (tid >> 1))*Ks;
    const __nv_bfloat16* gB = B + z*strideB + (size_t)(n0 + (tid >> 1))*Ks;
    const int lrow  = tid >> 1;
    const int lhalf = (tid & 1) * 8;

    const uint32_t sa_base = smem_u32(As);
    const uint32_t sb_base = smem_u32(Bs);
    const int arow = lane & 15, asel = lane >> 4;
    const int brow = lane & 7,  bsel = (lane >> 3) & 1;

    float acc[4][4][4] = {};
    const int steps = Ks >> 4;

    uint4 pa = *(const uint4*)(gA + lhalf);
    uint4 pb = *(const uint4*)(gB + lhalf);

    #pragma unroll 1
    for (int s = 0; s < steps; s++) {
        const int buf = s & 1;
        *(uint4*)&As[buf][lrow*24 + lhalf] = pa;
        *(uint4*)&Bs[buf][lrow*24 + lhalf] = pb;
        __syncthreads();

        if (s + 1 < steps) {
            const int k0 = (s + 1) * 16;
            pa = *(const uint4*)(gA + k0 + lhalf);
            pb = *(const uint4*)(gB + k0 + lhalf);
        }

        uint32_t afr[4][4];
        #pragma unroll
        for (int i = 0; i < 4; i++) {
            const int row = wm*64 + i*16 + arow;
            const uint32_t addr = sa_base + (uint32_t)(buf*128*24 + row*24 + asel*8) * 2;
            asm volatile("ldmatrix.sync.aligned.m8n8.x4.shared.b16 {%0,%1,%2,%3}, [%4];"
                : "=r"(afr[i][0]), "=r"(afr[i][1]), "=r"(afr[i][2]), "=r"(afr[i][3]) : "r"(addr));
        }
        uint32_t bfr[4][2];
        #pragma unroll
        for (int j = 0; j < 4; j++) {
            const int row = wn*32 + j*8 + brow;
            const uint32_t addr = sb_base + (uint32_t)(buf*128*24 + row*24 + bsel*8) * 2;
            asm volatile("ldmatrix.sync.aligned.m8n8.x2.shared.b16 {%0,%1}, [%2];"
                : "=r"(bfr[j][0]), "=r"(bfr[j][1]) : "r"(addr));
        }
        #pragma unroll
        for (int i = 0; i < 4; i++)
            #pragma unroll
            for (int j = 0; j < 4; j++)
                asm volatile(
                    "mma.sync.aligned.m16n8k16.row.col.f32.bf16.bf16.f32 "
                    "{%0,%1,%2,%3}, {%4,%5,%6,%7}, {%8,%9}, {%0,%1,%2,%3};"
                    : "+f"(acc[i][j][0]), "+f"(acc[i][j][1]), "+f"(acc[i][j][2]), "+f"(acc[i][j][3])
                    : "r"(afr[i][0]), "r"(afr[i][1]), "r"(afr[i][2]), "r"(afr[i][3]),
                      "r"(bfr[j][0]), "r"(bfr[j][1]));
    }

    float* Cz = C + z*strideC;
    const int gr = lane >> 2, gc = (lane & 3) * 2;
    #pragma unroll
    for (int i = 0; i < 4; i++) {
        const int r0 = bm + wm*64 + i*16 + gr;
        const int r1 = r0 + 8;
        float bi0 = 0.f, bi1 = 0.f;
        if (bias0) {
            const float* bp0 = (r0 < 256) ? bias0 : (r0 < 512) ? bias1 : bias2;
            const float* bp1 = (r1 < 256) ? bias0 : (r1 < 512) ? bias1 : bias2;
            bi0 = bp0[r0 & 255];
            bi1 = bp1[r1 & 255];
        }
        #pragma unroll
        for (int j = 0; j < 4; j++) {
            const int col = n0 + wn*32 + j*8 + gc;
            if (col < NTOK) {
                *(float2*)&Cz[(size_t)r0*NTOK + col] = make_float2(acc[i][j][0] + bi0, acc[i][j][1] + bi0);
                *(float2*)&Cz[(size_t)r1*NTOK + col] = make_float2(acc[i][j][2] + bi1, acc[i][j][3] + bi1);
            }
        }
    }
}

// ---------------- build bf16-split stacked operands + init g_rmax ----------------
__global__ void build_xy() {
    __shared__ float ta[32][33], tb[32][33];
    const int n0 = blockIdx.x * 32, c0 = blockIdx.y * 32, z = blockIdx.z;
    const int b = z >> 2, h = z & 3;
    const int tx = threadIdx.x, ty = threadIdx.y;    // 32 x 8
    if (blockIdx.y == 0 && ty == 0) g_rmax[z*NPAD + n0 + tx] = -1e30f;
    #pragma unroll
    for (int r = 0; r < 4; r++) {
        int col = c0 + ty + r*8;
        int n = n0 + tx;
        float va = 0.f, vb = 0.f;
        if (n < NTOK) {
            if (col < 64) {
                va = g_qkv[((size_t)b*768 + h*64 + col)*NTOK + n];
                vb = g_qkv[((size_t)b*768 + 256 + h*64 + col)*NTOK + n];
            } else {
                va = g_rel[(size_t)(h*64 + col - 64)*NTOK + n];
                vb = g_qkv[((size_t)b*768 + h*64 + col - 64)*NTOK + n];
            }
        }
        ta[ty + r*8][tx] = va;
        tb[ty + r*8][tx] = vb;
    }
    __syncthreads();
    #pragma unroll
    for (int r = 0; r < 4; r++) {
        int n = n0 + ty + r*8;
        size_t base = ((size_t)z*NPAD + n)*KSTACK;
        int col = c0 + tx;
        float va = ta[tx][ty + r*8];
        float vb = tb[tx][ty + r*8];
        __nv_bfloat16 ha = __float2bfloat16(va);
        __nv_bfloat16 la = __float2bfloat16(va - __bfloat162float(ha));
        __nv_bfloat16 hb = __float2bfloat16(vb);
        __nv_bfloat16 lb = __float2bfloat16(vb - __bfloat162float(hb));
        g_xa[base + col]       = ha;
        g_xa[base + 128 + col] = la;
        g_xa[base + 256 + col] = ha;
        g_yb[base + col]       = hb;
        g_yb[base + 128 + col] = hb;
        g_yb[base + 256 + col] = lb;
    }
}

// ---------------- V split ----------------
__global__ void vsplit() {
    __shared__ float t[32][33];
    const int m0 = blockIdx.x * 32, c0 = blockIdx.y * 32, z = blockIdx.z;
    const int b = z >> 2, h = z & 3;
    const int tx = threadIdx.x, ty = threadIdx.y;   // 32 x 8
    #pragma unroll
    for (int r = 0; r < 4; r++) {
        int c = c0 + ty + r*8;
        int m = m0 + tx;
        t[ty + r*8][tx] = (m < NTOK) ? g_qkv[((size_t)b*768 + 512 + h*64 + c)*NTOK + m] : 0.f;
    }
    __syncthreads();
    #pragma unroll
    for (int r = 0; r < 4; r++) {
        int m = m0 + ty + r*8;
        float v = t[tx][ty + r*8];
        __nv_bfloat16 hi = __float2bfloat16(v);
        __nv_bfloat16 lo = __float2bfloat16(v - __bfloat162float(hi));
        size_t idx = ((size_t)z*NPAD + m)*DHEAD + c0 + tx;
        g_vhi[idx] = hi;
        g_vlo[idx] = lo;
    }
}

// ---------------- HMMA S-tile kernel + row-max atomics ----------------
__global__ __launch_bounds__(256) void tn_s_mma() {
    __shared__ __nv_bfloat16 As[2][128*24];
    __shared__ __nv_bfloat16 Bs[2][128*24];
    const int tid = threadIdx.x;
    const int warp = tid >> 5, lane = tid & 31;
    const int wm = warp >> 2, wn = warp & 3;
    const int z = blockIdx.z;
    const int n0 = blockIdx.y * 128, m0 = blockIdx.x * 128;

    const __nv_bfloat16* xa = g_xa + ((size_t)z*NPAD + n0)*KSTACK;
    const __nv_bfloat16* yb = g_yb + ((size_t)z*NPAD + m0)*KSTACK;

    const int lrow  = tid >> 1;
    const int lhalf = (tid & 1) * 8;

    const uint32_t sa_base = smem_u32(As);
    const uint32_t sb_base = smem_u32(Bs);
    const int arow = lane & 15, asel = lane >> 4;
    const int brow = lane & 7,  bsel = (lane >> 3) & 1;

    float acc[4][4][4] = {};

    uint4 pa = *(const uint4*)(xa + (size_t)lrow*KSTACK + lhalf);
    uint4 pb = *(const uint4*)(yb + (size_t)lrow*KSTACK + lhalf);

    #pragma unroll 1
    for (int s = 0; s < 24; s++) {
        const int buf = s & 1;
        *(uint4*)&As[buf][lrow*24 + lhalf] = pa;
        *(uint4*)&Bs[buf][lrow*24 + lhalf] = pb;
        __syncthreads();

        if (s + 1 < 24) {
            const int k0 = (s + 1) * 16;
            pa = *(const uint4*)(xa + (size_t)lrow*KSTACK + k0 + lhalf);
            pb = *(const uint4*)(yb + (size_t)lrow*KSTACK + k0 + lhalf);
        }

        uint32_t afr[4][4];
        #pragma unroll
        for (int i = 0; i < 4; i++) {
            const int row = wm*64 + i*16 + arow;
            const uint32_t addr = sa_base + (uint32_t)(buf*128*24 + row*24 + asel*8) * 2;
            asm volatile("ldmatrix.sync.aligned.m8n8.x4.shared.b16 {%0,%1,%2,%3}, [%4];"
                : "=r"(afr[i][0]), "=r"(afr[i][1]), "=r"(afr[i][2]), "=r"(afr[i][3]) : "r"(addr));
        }
        uint32_t bfr[4][2];
        #pragma unroll
        for (int j = 0; j < 4; j++) {
            const int row = wn*32 + j*8 + brow;
            const uint32_t addr = sb_base + (uint32_t)(buf*128*24 + row*24 + bsel*8) * 2;
            asm volatile("ldmatrix.sync.aligned.m8n8.x2.shared.b16 {%0,%1}, [%2];"
                : "=r"(bfr[j][0]), "=r"(bfr[j][1]) : "r"(addr));
        }
        #pragma unroll
        for (int i = 0; i < 4; i++)
            #pragma unroll
            for (int j = 0; j < 4; j++)
                asm volatile(
                    "mma.sync.aligned.m16n8k16.row.col.f32.bf16.bf16.f32 "
                    "{%0,%1,%2,%3}, {%4,%5,%6,%7}, {%8,%9}, {%0,%1,%2,%3};"
                    : "+f"(acc[i][j][0]), "+f"(acc[i][j][1]), "+f"(acc[i][j][2]), "+f"(acc[i][j][3])
                    : "r"(afr[i][0]), "r"(afr[i][1]), "r"(afr[i][2]), "r"(afr[i][3]),
                      "r"(bfr[j][0]), "r"(bfr[j][1]));
    }

    float* C = g_S + (size_t)z*NTOK*NTOK;
    const int gr = lane >> 2, gc = (lane & 3) * 2;
    #pragma unroll
    for (int i = 0; i < 4; i++) {
        const int r0 = n0 + wm*64 + i*16 + gr;
        const int r1 = r0 + 8;
        float mr0 = -1e30f, mr1 = -1e30f;
        #pragma unroll
        for (int j = 0; j < 4; j++) {
            const int col = m0 + wn*32 + j*8 + gc;
            if (col < NTOK) {
                mr0 = fmaxf(mr0, acc[i][j][0]);
                mr1 = fmaxf(mr1, acc[i][j][2]);
                if (r0 < NTOK) *(float2*)&C[(size_t)r0*NTOK + col] = make_float2(acc[i][j][0], acc[i][j][1]);
                if (r1 < NTOK) *(float2*)&C[(size_t)r1*NTOK + col] = make_float2(acc[i][j][2], acc[i][j][3]);
            }
            if (col + 1 < NTOK) {
                mr0 = fmaxf(mr0, acc[i][j][1]);
                mr1 = fmaxf(mr1, acc[i][j][3]);
            }
        }
        // reduce over the 4-lane column group (xor 1, 2 stay within lane&3 group)
        mr0 = fmaxf(mr0, __shfl_xor_sync(0xffffffffu, mr0, 1));
        mr0 = fmaxf(mr0, __shfl_xor_sync(0xffffffffu, mr0, 2));
        mr1 = fmaxf(mr1, __shfl_xor_sync(0xffffffffu, mr1, 1));
        mr1 = fmaxf(mr1, __shfl_xor_sync(0xffffffffu, mr1, 2));
        if ((lane & 3) == 0) {
            if (r0 < NTOK) atomicMaxF(&g_rmax[z*NPAD + r0], mr0);
            if (r1 < NTOK) atomicMaxF(&g_rmax[z*NPAD + r1], mr1);
        }
    }
}

// ---------------- HMMA AV kernel: inline exp + inline row-sum, divide at end ----------------
__global__ __launch_bounds__(256) void av_mma() {
    extern __shared__ __nv_bfloat16 dsm[];
    __nv_bfloat16* Ahi = dsm;
    __nv_bfloat16* Alo = Ahi + 128*72;
    __nv_bfloat16* Bhi = Alo + 128*72;
    __nv_bfloat16* Blo = Bhi + 64*72;
    __shared__ float Ls[128][2];

    const int tid = threadIdx.x;
    const int warp = tid >> 5, lane = tid & 31;
    const int wn = warp >> 1, wd = warp & 1;
    const int z = blockIdx.y, b = z >> 2, h = z & 3;
    const int n0 = blockIdx.x * 128;

    const int lr = tid >> 1;
    const int lch = (tid & 1) * 32;
    const int n_ld = n0 + lr;
    const bool rowok = n_ld < NTOK;
    const float mx = rowok ? g_rmax[z*NPAD + n_ld] : 0.f;
    const float* Srow = g_S + (size_t)z*NTOK*NTOK + (size_t)n_ld*NTOK;

    const uint32_t sa_hi = smem_u32(Ahi);
    const uint32_t sa_lo = smem_u32(Alo);
    const uint32_t sb_hi = smem_u32(Bhi);
    const uint32_t sb_lo = smem_u32(Blo);

    float acc[2][4][4] = {};
    float lsum = 0.f;

    for (int ch = 0; ch < 43; ch++) {
        const int mc = ch * 64;
        __syncthreads();

        #pragma unroll
        for (int i = 0; i < 8; i++) {
            const int m = mc + lch + i*4;
            float4 pv = make_float4(0.f,0.f,0.f,0.f);
            if (rowok && m < NTOK) {
                float4 s = *(const float4*)(Srow + m);
                pv.x = exp2f((s.x - mx) * LOG2E);
                pv.y = exp2f((s.y - mx) * LOG2E);
                pv.z = exp2f((s.z - mx) * LOG2E);
                pv.w = exp2f((s.w - mx) * LOG2E);
                lsum += pv.x + pv.y + pv.z + pv.w;
            }
            __nv_bfloat162 h01 = __floats2bfloat162_rn(pv.x, pv.y);
            __nv_bfloat162 h23 = __floats2bfloat162_rn(pv.z, pv.w);
            __nv_bfloat162 l01 = __floats2bfloat162_rn(pv.x - __bfloat162float(__low2bfloat16(h01)),
                                                       pv.y - __bfloat162float(__high2bfloat16(h01)));
            __nv_bfloat162 l23 = __floats2bfloat162_rn(pv.z - __bfloat162float(__low2bfloat16(h23)),
                                                       pv.w - __bfloat162float(__high2bfloat16(h23)));
            const int o = lr*72 + lch + i*4;
            *(__nv_bfloat162*)(Ahi + o)     = h01;
            *(__nv_bfloat162*)(Ahi + o + 2) = h23;
            *(__nv_bfloat162*)(Alo + o)     = l01;
            *(__nv_bfloat162*)(Alo + o + 2) = l23;
        }
        #pragma unroll
        for (int i = 0; i < 2; i++) {
            const int idx = tid + 256*i;
            const int row = idx >> 3, seg = (idx & 7) * 8;
            const size_t gsrc = ((size_t)z*NPAD + mc + row)*DHEAD + seg;
            *(uint4*)(Bhi + row*72 + seg) = *(const uint4*)(g_vhi + gsrc);
            *(uint4*)(Blo + row*72 + seg) = *(const uint4*)(g_vlo + gsrc);
        }
        __syncthreads();

        #pragma unroll
        for (int step = 0; step < 4; step++) {
            const int k0 = step * 16;
            uint32_t ah[2][4], al[2][4];
            #pragma unroll
            for (int i = 0; i < 2; i++) {
                const uint32_t off = (uint32_t)((wn*32 + i*16 + (lane & 15))*72 + k0 + ((lane >> 4) << 3)) * 2;
                asm volatile("ldmatrix.sync.aligned.m8n8.x4.shared.b16 {%0,%1,%2,%3}, [%4];"
                    : "=r"(ah[i][0]), "=r"(ah[i][1]), "=r"(ah[i][2]), "=r"(ah[i][3]) : "r"(sa_hi + off));
                asm volatile("ldmatrix.sync.aligned.m8n8.x4.shared.b16 {%0,%1,%2,%3}, [%4];"
                    : "=r"(al[i][0]), "=r"(al[i][1]), "=r"(al[i][2]), "=r"(al[i][3]) : "r"(sa_lo + off));
            }
            uint32_t bh[2][4], bl[2][4];
            #pragma unroll
            for (int jj = 0; jj < 2; jj++) {
                const int d0 = wd*32 + jj*16;
                const uint32_t off = (uint32_t)((k0 + (lane & 7) + ((lane >> 3) & 1)*8)*72 + d0 + ((lane >> 4) << 3)) * 2;
                asm volatile("ldmatrix.sync.aligned.m8n8.x4.trans.shared.b16 {%0,%1,%2,%3}, [%4];"
                    : "=r"(bh[jj][0]), "=r"(bh[jj][1]), "=r"(bh[jj][2]), "=r"(bh[jj][3]) : "r"(sb_hi + off));
                asm volatile("ldmatrix.sync.aligned.m8n8.x4.trans.shared.b16 {%0,%1,%2,%3}, [%4];"
                    : "=r"(bl[jj][0]), "=r"(bl[jj][1]), "=r"(bl[jj][2]), "=r"(bl[jj][3]) : "r"(sb_lo + off));
            }
            #define AV_MMA(ac, af, b0, b1) \
                asm volatile("mma.sync.aligned.m16n8k16.row.col.f32.bf16.bf16.f32 " \
                    "{%0,%1,%2,%3}, {%4,%5,%6,%7}, {%8,%9}, {%0,%1,%2,%3};" \
                    : "+f"((ac)[0]), "+f"((ac)[1]), "+f"((ac)[2]), "+f"((ac)[3]) \
                    : "r"((af)[0]), "r"((af)[1]), "r"((af)[2]), "r"((af)[3]), "r"(b0), "r"(b1))
            #pragma unroll
            for (int i = 0; i < 2; i++)
                #pragma unroll
                for (int jj = 0; jj < 2; jj++) {
                    AV_MMA(acc[i][jj*2+0], ah[i], bh[jj][0], bh[jj][1]);
                    AV_MMA(acc[i][jj*2+1], ah[i], bh[jj][2], bh[jj][3]);
                    AV_MMA(acc[i][jj*2+0], al[i], bh[jj][0], bh[jj][1]);
                    AV_MMA(acc[i][jj*2+1], al[i], bh[jj][2], bh[jj][3]);
                    AV_MMA(acc[i][jj*2+0], ah[i], bl[jj][0], bl[jj][1]);
                    AV_MMA(acc[i][jj*2+1], ah[i], bl[jj][2], bl[jj][3]);
                }
            #undef AV_MMA
        }
    }

    // publish row sums, then normalize in epilogue
    Ls[lr][tid & 1] = lsum;
    __syncthreads();

    const int baseCh = b*CMID + h*DHEAD;
    const int gr = lane >> 2, gc = (lane & 3) * 2;
    #pragma unroll
    for (int i = 0; i < 2; i++) {
        const int lr0 = wn*32 + i*16 + gr;
        const int lr1 = lr0 + 8;
        const int r0 = n0 + lr0;
        const int r1 = n0 + lr1;
        const float inv0 = 1.f / (Ls[lr0][0] + Ls[lr0][1]);
        const float inv1 = 1.f / (Ls[lr1][0] + Ls[lr1][1]);
        #pragma unroll
        for (int j = 0; j < 4; j++) {
            const int d = wd*32 + j*8 + gc;
            float* c0p = g_ao + (size_t)(baseCh + d)*NTOK;
            float* c1p = g_ao + (size_t)(baseCh + d + 1)*NTOK;
            if (r0 < NTOK) { c0p[r0] = acc[i][j][0]*inv0; c1p[r0] = acc[i][j][1]*inv0; }
            if (r1 < NTOK) { c0p[r1] = acc[i][j][2]*inv1; c1p[r1] = acc[i][j][3]*inv1; }
        }
    }
}

// ---------------- BatchNorm ----------------
__global__ __launch_bounds__(256) void bn_stats(const float* __restrict__ x, int C,
                                                float* __restrict__ mean, float* __restrict__ istd) {
    const int c = blockIdx.x;
    const int tid = threadIdx.x;
    const int lane = tid & 31, wid = tid >> 5;
    float s = 0.f, sq = 0.f;
    for (int i = tid; i < BATCH*NTOK; i += 256) {
        int b = i / NTOK, n = i - b*NTOK;
        float v = x[((long)b*C + c)*NTOK + n];
        s += v; sq += v*v;
    }
    #pragma unroll
    for (int d = 16; d > 0; d >>= 1) {
        s  += __shfl_xor_sync(0xffffffffu, s, d);
        sq += __shfl_xor_sync(0xffffffffu, sq, d);
    }
    __shared__ float r1[8], r2[8];
    if (lane == 0) { r1[wid] = s; r2[wid] = sq; }
    __syncthreads();
    if (tid == 0) {
        float S1 = 0.f, S2 = 0.f;
        #pragma unroll
        for (int w = 0; w < 8; w++) { S1 += r1[w]; S2 += r2[w]; }
        const float inv_cnt = 1.f / (BATCH*NTOK);
        float m = S1 * inv_cnt;
        float var = S2 * inv_cnt - m*m;
        mean[c] = m;
        istd[c] = rsqrtf(var + 1e-5f);
    }
}

__global__ void bn_res_relu(const float* __restrict__ y, const float* __restrict__ xres,
                            float* __restrict__ out,
                            const float* __restrict__ mean, const float* __restrict__ istd,
                            const float* __restrict__ g, const float* __restrict__ bp) {
    long idx = (long)blockIdx.x * 256 + threadIdx.x;
    if (idx >= (long)BATCH*COUT*NTOK) return;
    int c = (int)((idx / NTOK) % COUT);
    float v = (y[idx] - mean[c]) * istd[c] * g[c] + bp[c] + xres[idx];
    out[idx] = fmaxf(v, 0.f);
}

// ---------------- launch ----------------
extern "C" void kernel_launch(void* const* d_in, const int* in_sizes, int n_in,
                              void* d_out, int out_size) {
    const float* x    = (const float*)d_in[0];
    const float* W1   = (const float*)d_in[1];
    const float* g1   = (const float*)d_in[2];
    const float* b1   = (const float*)d_in[3];
    const float* Wq   = (const float*)d_in[4];
    const float* bq   = (const float*)d_in[5];
    const float* Wk   = (const float*)d_in[6];
    const float* bk   = (const float*)d_in[7];
    const float* Wv   = (const float*)d_in[8];
    const float* bv   = (const float*)d_in[9];
    const float* relh = (const float*)d_in[10];
    const float* relw = (const float*)d_in[11];
    const float* reld = (const float*)d_in[12];
    const float* g2   = (const float*)d_in[13];
    const float* b2   = (const float*)d_in[14];
    const float* W3   = (const float*)d_in[15];
    const float* g3   = (const float*)d_in[16];
    const float* b3   = (const float*)d_in[17];
    float* out = (float*)d_out;

    float *y1, *ao, *y3, *mean, *istd, *qkv;
    __nv_bfloat16 *w1st, *wqkvst, *w3st, *xst, *y1st, *aost;
    cudaGetSymbolAddress((void**)&y1,  g_y1);
    cudaGetSymbolAddress((void**)&ao,  g_ao);
    cudaGetSymbolAddress((void**)&y3,  g_y3);
    cudaGetSymbolAddress((void**)&mean,g_mean);
    cudaGetSymbolAddress((void**)&istd,g_istd);
    cudaGetSymbolAddress((void**)&qkv, g_qkv);
    cudaGetSymbolAddress((void**)&w1st,  g_w1st);
    cudaGetSymbolAddress((void**)&wqkvst,g_wqkvst);
    cudaGetSymbolAddress((void**)&w3st,  g_w3st);
    cudaGetSymbolAddress((void**)&xst,   g_xst);
    cudaGetSymbolAddress((void**)&y1st,  g_y1st);
    cudaGetSymbolAddress((void**)&aost,  g_aost);

    const dim3 blk(256);
    const int NT = (NTOK + 127) / 128;        // 22
    const int NT32 = NPAD / 32;               // 88
    const int AV_SMEM = (2*128*72 + 2*64*72) * 2;
    cudaFuncSetAttribute(av_mma, cudaFuncAttributeMaxDynamicSharedMemorySize, AV_SMEM);

    // weight splits
    wsplit<<<(CMID*CIN + 255)/256, blk>>>(W1, w1st, CMID*CIN, CIN);
    wsplit<<<(CMID*CMID + 255)/256, blk>>>(Wq, wqkvst,                    CMID*CMID, CMID);
    wsplit<<<(CMID*CMID + 255)/256, blk>>>(Wk, wqkvst + (size_t)256*768,  CMID*CMID, CMID);
    wsplit<<<(CMID*CMID + 255)/256, blk>>>(Wv, wqkvst + (size_t)512*768,  CMID*CMID, CMID);
    wsplit<<<(COUT*CMID + 255)/256, blk>>>(W3, w3st, COUT*CMID, CMID);

    // x split -> conv1 (HMMA)
    xsplit<<<dim3(NT32, CIN/32, BATCH), dim3(32,8)>>>(x, xst, CIN,
        (long)CIN*NTOK, (long)NPAD*3*CIN, nullptr, nullptr, nullptr, nullptr);
    gemm_hmma<<<dim3(NT, 2, BATCH), blk>>>(w1st, xst, y1, 3*CIN,
        (long)NPAD*3*CIN, (long)CMID*NTOK, nullptr, nullptr, nullptr);
    bn_stats<<<CMID, 256>>>(y1, CMID, mean, istd);

    // BN1+ReLU fused into split -> qkv (HMMA, stacked M=768)
    xsplit<<<dim3(NT32, CMID/32, BATCH), dim3(32,8)>>>(y1, y1st, CMID,
        (long)CMID*NTOK, (long)NPAD*3*CMID, mean, istd, g1, b1);
    gemm_hmma<<<dim3(NT, 6, BATCH), blk>>>(wqkvst, y1st, qkv, 3*CMID,
        (long)NPAD*3*CMID, (long)768*NTOK, bq, bk, bv);

    // rel tensor + attention operand prep (build_xy also inits g_rmax)
    build_rel_kernel<<<(NHEADS*DHEAD*NTOK)/256, 256>>>(relh, relw, reld);
    build_xy<<<dim3(NT32, 4, BATCH*NHEADS), dim3(32,8)>>>();
    vsplit<<<dim3(NT32, 2, BATCH*NHEADS), dim3(32,8)>>>();

    // attention: logits+rowmax (HMMA) -> AV (HMMA, softmax+rowsum inline)
    tn_s_mma<<<dim3(NT, NT, BATCH*NHEADS), blk>>>();
    av_mma<<<dim3(NT, BATCH*NHEADS), blk, AV_SMEM>>>();

    // BN2+ReLU fused into split -> conv3 (HMMA)
    bn_stats<<<CMID, 256>>>(ao, CMID, mean, istd);
    xsplit<<<dim3(NT32, CMID/32, BATCH), dim3(32,8)>>>(ao, aost, CMID,
        (long)CMID*NTOK, (long)NPAD*3*CMID, mean, istd, g2, b2);
    gemm_hmma<<<dim3(NT, 8, BATCH), blk>>>(w3st, aost, y3, 3*CMID,
        (long)NPAD*3*CMID, (long)COUT*NTOK, nullptr, nullptr, nullptr);

    // BN3 + residual + ReLU
    bn_stats<<<COUT, 256>>>(y3, COUT, mean, istd);
    bn_res_relu<<<(BATCH*COUT*NTOK)/256, 256>>>(y3, x, out, mean, istd, g3, b3);
}